// round 8
// baseline (speedup 1.0000x reference)
#include <cuda_runtime.h>
#include <cstdint>

#define IN_DIM    4096
#define OUT_DIM   1024
#define NROWS     16384
#define NCHUNK    16
#define CHUNK     256            // columns per shared chunk
#define PITCH     129            // floats per column row (odd -> conflict-free: bank = c + n)
#define XS_FLOATS (CHUNK * PITCH)          // 33024 floats = 132096 B
#define EBCAP     192
#define NWARPS    16
#define SMEM_BYTES (XS_FLOATS * 4 + NWARPS * EBCAP * 4)   // 132096 + 12288 = 144384
#define SCALE     0.3162277660168379f   // 1/sqrt(10)

// Precomputed sparse structure (rebuilt every launch; deterministic).
// Entry: low 31 bits = c_local * PITCH (float index into chunk plane), bit31 = sign.
__device__ unsigned int g_ent[40960];
__device__ int g_cnt[NCHUNK * OUT_DIM];
__device__ int g_off[NCHUNK * OUT_DIM + 1];

// ---------------------------------------------------------------------------
// Prep 1: count nonzeros per (chunk, output-row) cell. One warp per row.
__global__ void jl_count(const float* __restrict__ Phi) {
    int w = threadIdx.x >> 5, lane = threadIdx.x & 31;
    int r = blockIdx.x * 8 + w;
    const float* row = Phi + (size_t)r * IN_DIM;
    #pragma unroll
    for (int ch = 0; ch < NCHUNK; ++ch) {
        int c = 0;
        #pragma unroll
        for (int b = 0; b < CHUNK; b += 32) {
            float v = row[ch * CHUNK + b + lane];
            unsigned m = __ballot_sync(0xffffffffu, v != 0.0f);
            c += __popc(m);
        }
        if (lane == 0) g_cnt[ch * OUT_DIM + r] = c;
    }
}

// ---------------------------------------------------------------------------
// Prep 2: exclusive scan over the 16384 cell counts (chunk-major order).
__global__ void jl_scan() {
    __shared__ int sh[1024];
    int t = threadIdx.x;
    int loc[16];
    int s = 0;
    #pragma unroll
    for (int q = 0; q < 16; ++q) { loc[q] = s; s += g_cnt[t * 16 + q]; }
    sh[t] = s;
    __syncthreads();
    for (int d = 1; d < 1024; d <<= 1) {
        int v = 0;
        if (t >= d) v = sh[t - d];
        __syncthreads();
        sh[t] += v;
        __syncthreads();
    }
    int ex = (t == 0) ? 0 : sh[t - 1];
    #pragma unroll
    for (int q = 0; q < 16; ++q) g_off[t * 16 + q] = ex + loc[q];
    if (t == 1023) g_off[NCHUNK * OUT_DIM] = sh[1023];
}

// ---------------------------------------------------------------------------
// Prep 3: fill compact chunk-major entry array (ballot/popc compaction).
__global__ void jl_fill(const float* __restrict__ Phi) {
    int w = threadIdx.x >> 5, lane = threadIdx.x & 31;
    int r = blockIdx.x * 8 + w;
    const float* row = Phi + (size_t)r * IN_DIM;
    unsigned lmask = (1u << lane) - 1u;
    for (int ch = 0; ch < NCHUNK; ++ch) {
        int pos = g_off[ch * OUT_DIM + r];
        for (int b = 0; b < CHUNK; b += 32) {
            float v = row[ch * CHUNK + b + lane];
            bool nz = (v != 0.0f);
            unsigned m = __ballot_sync(0xffffffffu, nz);
            if (nz) {
                int idx = pos + __popc(m & lmask);
                unsigned cl = (unsigned)(b + lane);          // c within chunk, 0..255
                g_ent[idx] = cl * PITCH + (v < 0.0f ? 0x80000000u : 0u);
            }
            pos += __popc(m);
        }
    }
}

// ---------------------------------------------------------------------------
// Main: 512 blocks = 128 n-tiles x 4 row-quarters. Block = 512 thr (16 warps),
// covers 128 n x 256 output rows. Warp owns 16 rows; lane l accumulates
// n = l, l+32, l+64, l+96 (4 fp32 acc per row -> 64 acc regs).
// x chunk in shared as [256 c][pitch 129 floats]; bank = (c + n) mod 32 ->
// conflict-free STS (lanes = consecutive c) AND conflict-free gather
// (lanes = consecutive n).
__global__ __launch_bounds__(512, 1) void jl_main(const float* __restrict__ x,
                                                  float* __restrict__ out) {
    extern __shared__ float xs[];
    unsigned* eb_all = (unsigned*)(xs + XS_FLOATS);
    int tid  = threadIdx.x;
    int lane = tid & 31, w = tid >> 5;
    int nt = blockIdx.x >> 2, rq = blockIdx.x & 3;
    int n0 = nt << 7;                       // n-tile base (128 n per block)
    int rbase = (rq << 8) + (w << 4);       // this warp's 16 rows
    unsigned* eb = eb_all + w * EBCAP;

    float acc[16][4];
    #pragma unroll
    for (int i = 0; i < 16; ++i) {
        acc[i][0] = 0.0f; acc[i][1] = 0.0f; acc[i][2] = 0.0f; acc[i][3] = 0.0f;
    }

    // x-load mapping: thread = (column cl, n-group ng); lanes hit consecutive
    // columns -> coalesced 128B LDG, conflict-free STS.
    int cl = tid & 255;
    int ng = tid >> 8;                      // 0..1, covers 64 n each
    const float* xg0 = x + (size_t)(n0 + ng * 64) * IN_DIM + cl;
    float* xsd = xs + cl * PITCH + ng * 64;

    int olane = (lane < 17) ? lane : 16;    // lanes 0..16 carry segment offsets

    for (int ch = 0; ch < NCHUNK; ++ch) {
        if (ch) __syncthreads();            // xs free (previous gather done)

        // per-warp segment offsets for its 16 rows (17 boundary values)
        int o1 = g_off[ch * OUT_DIM + rbase + olane];
        int S = __shfl_sync(0xffffffffu, o1, 0);
        int E = __shfl_sync(0xffffffffu, o1, 16);

        // stage entry span (warp-private; LDG latency hides under x loads)
        for (int k = S + lane; k < E; k += 32) {
            int d = k - S;
            if (d < EBCAP) eb[d] = g_ent[k];
        }

        // load x chunk: 256 c x 128 n
        const float* xg = xg0 + ch * CHUNK;
        #pragma unroll 16
        for (int k = 0; k < 64; ++k) {
            xsd[k] = xg[(size_t)k * IN_DIM];
        }
        __syncthreads();                    // xs + eb ready

        // gather + FFMA accumulate
        const float* xb = xs + lane;
        #pragma unroll
        for (int i = 0; i < 16; ++i) {
            int b = __shfl_sync(0xffffffffu, o1, i) - S;
            int e = __shfl_sync(0xffffffffu, o1, i + 1) - S;
            for (int j = b; j < e; ++j) {
                unsigned t = eb[j];
                float sg = __int_as_float(0x3f800000u | (t & 0x80000000u));
                const float* p = xb + (t & 0x7fffffffu);
                acc[i][0] = fmaf(sg, p[0],   acc[i][0]);   // n = lane
                acc[i][1] = fmaf(sg, p[32],  acc[i][1]);   // n = lane + 32
                acc[i][2] = fmaf(sg, p[64],  acc[i][2]);   // n = lane + 64
                acc[i][3] = fmaf(sg, p[96],  acc[i][3]);   // n = lane + 96
            }
        }
    }
    __syncthreads();

    // epilogue: stage [256 r][pitch 129 n] in xs, then coalesced stores
    #pragma unroll
    for (int i = 0; i < 16; ++i) {
        float* row = xs + ((w << 4) + i) * PITCH + lane;
        row[0]  = acc[i][0] * SCALE;
        row[32] = acc[i][1] * SCALE;
        row[64] = acc[i][2] * SCALE;
        row[96] = acc[i][3] * SCALE;
    }
    __syncthreads();

    int rr = tid & 255;
    int nn = tid >> 8;
    float* ob = out + (size_t)n0 * OUT_DIM + (rq << 8) + rr;
    #pragma unroll 16
    for (int k = 0; k < 64; ++k) {
        int n = nn + k * 2;
        ob[(size_t)n * OUT_DIM] = xs[rr * PITCH + n];
    }
}

// ---------------------------------------------------------------------------
extern "C" void kernel_launch(void* const* d_in, const int* in_sizes, int n_in,
                              void* d_out, int out_size) {
    const float* x   = (const float*)d_in[0];
    const float* Phi = (const float*)d_in[1];
    float* out = (float*)d_out;

    cudaFuncSetAttribute(jl_main, cudaFuncAttributeMaxDynamicSharedMemorySize,
                         SMEM_BYTES);

    jl_count<<<128, 256>>>(Phi);
    jl_scan<<<1, 1024>>>();
    jl_fill<<<128, 256>>>(Phi);
    jl_main<<<512, 512, SMEM_BYTES>>>(x, out);
}

// round 10
// speedup vs baseline: 1.0413x; 1.0413x over previous
#include <cuda_runtime.h>
#include <cstdint>

#define IN_DIM    4096
#define OUT_DIM   1024
#define NROWS     16384
#define NCHUNK    16
#define CHUNK     256             // columns per shared chunk
#define PITCH2    65              // float2 per column row (odd -> conflict-free LDS.64)
#define XS_F2     (CHUNK * PITCH2)       // 16640 float2 = 133120 B
#define EBCAP     192
#define NWARPS    16
#define SMEM_BYTES (XS_F2 * 8 + NWARPS * EBCAP * 4)   // 133120 + 12288 = 145408
#define SCALE     0.3162277660168379f   // 1/sqrt(10)

// Precomputed sparse structure (rebuilt every launch; deterministic).
// Entry: low 31 bits = c_local * PITCH2 (float2 index into chunk plane), bit31 = sign.
__device__ unsigned int g_ent[40960];
__device__ int g_cnt[NCHUNK * OUT_DIM];
__device__ int g_off[NCHUNK * OUT_DIM + 1];

// ---------------------------------------------------------------------------
// Prep 1: count nonzeros per (chunk, output-row) cell. One warp per row.
__global__ void jl_count(const float* __restrict__ Phi) {
    int w = threadIdx.x >> 5, lane = threadIdx.x & 31;
    int r = blockIdx.x * 8 + w;
    const float* row = Phi + (size_t)r * IN_DIM;
    #pragma unroll
    for (int ch = 0; ch < NCHUNK; ++ch) {
        int c = 0;
        #pragma unroll
        for (int b = 0; b < CHUNK; b += 32) {
            float v = row[ch * CHUNK + b + lane];
            unsigned m = __ballot_sync(0xffffffffu, v != 0.0f);
            c += __popc(m);
        }
        if (lane == 0) g_cnt[ch * OUT_DIM + r] = c;
    }
}

// ---------------------------------------------------------------------------
// Prep 2: exclusive scan over the 16384 cell counts (chunk-major order).
__global__ void jl_scan() {
    __shared__ int sh[1024];
    int t = threadIdx.x;
    int loc[16];
    int s = 0;
    #pragma unroll
    for (int q = 0; q < 16; ++q) { loc[q] = s; s += g_cnt[t * 16 + q]; }
    sh[t] = s;
    __syncthreads();
    for (int d = 1; d < 1024; d <<= 1) {
        int v = 0;
        if (t >= d) v = sh[t - d];
        __syncthreads();
        sh[t] += v;
        __syncthreads();
    }
    int ex = (t == 0) ? 0 : sh[t - 1];
    #pragma unroll
    for (int q = 0; q < 16; ++q) g_off[t * 16 + q] = ex + loc[q];
    if (t == 1023) g_off[NCHUNK * OUT_DIM] = sh[1023];
}

// ---------------------------------------------------------------------------
// Prep 3: fill compact chunk-major entry array (ballot/popc compaction).
__global__ void jl_fill(const float* __restrict__ Phi) {
    int w = threadIdx.x >> 5, lane = threadIdx.x & 31;
    int r = blockIdx.x * 8 + w;
    const float* row = Phi + (size_t)r * IN_DIM;
    unsigned lmask = (1u << lane) - 1u;
    for (int ch = 0; ch < NCHUNK; ++ch) {
        int pos = g_off[ch * OUT_DIM + r];
        for (int b = 0; b < CHUNK; b += 32) {
            float v = row[ch * CHUNK + b + lane];
            bool nz = (v != 0.0f);
            unsigned m = __ballot_sync(0xffffffffu, nz);
            if (nz) {
                int idx = pos + __popc(m & lmask);
                unsigned cl = (unsigned)(b + lane);            // c within chunk, 0..255
                g_ent[idx] = cl * PITCH2 + (v < 0.0f ? 0x80000000u : 0u);
            }
            pos += __popc(m);
        }
    }
}

// ---------------------------------------------------------------------------
// Main: 512 blocks = 128 n-tiles x 4 row-quarters. Block = 512 thr (16 warps),
// covers 128 n x 256 output rows. Warp owns 16 rows; lane l accumulates
// n = 2l, 2l+1, 64+2l, 64+2l+1 (2 float2 acc per row -> 64 acc regs).
// x chunk in shared as [256 c][65 float2]; LDS.64 gather and STS.64 fill both
// conflict-free. Inner loop is a flat 3-stage software pipeline over the
// warp's whole entry stream: entry prefetch -> x prefetch -> FFMA, so every
// LDS has one full iteration of slack before its consumer.
__global__ __launch_bounds__(512, 1) void jl_main(const float* __restrict__ x,
                                                  float* __restrict__ out) {
    extern __shared__ float2 xs2[];
    unsigned* eb_all = (unsigned*)(xs2 + XS_F2);
    int tid  = threadIdx.x;
    int lane = tid & 31, w = tid >> 5;
    int nt = blockIdx.x >> 2, rq = blockIdx.x & 3;
    int n0 = nt << 7;                       // n-tile base (128 n per block)
    int rbase = (rq << 8) + (w << 4);       // this warp's 16 rows
    unsigned* eb = eb_all + w * EBCAP;

    float2 acc[16][2];
    #pragma unroll
    for (int i = 0; i < 16; ++i) {
        acc[i][0].x = 0.f; acc[i][0].y = 0.f;
        acc[i][1].x = 0.f; acc[i][1].y = 0.f;
    }

    // x-load mapping: thread = (column cc, n-half ng). Lanes hit consecutive
    // columns -> coalesced LDG; STS.64 bank-pair = cc mod 16 -> conflict-free.
    int cc = tid & 255;
    int ng = tid >> 8;                      // 0..1, covers n 0..63 / 64..127
    const float* xg0 = x + (size_t)(n0 + ng * 64) * IN_DIM + cc;
    float2* xsd = xs2 + cc * PITCH2 + ng * 32;

    int olane = (lane < 17) ? lane : 16;    // lanes 0..16 carry segment offsets

    for (int ch = 0; ch < NCHUNK; ++ch) {
        if (ch) __syncthreads();            // xs/eb free (previous gather done)

        // per-warp segment offsets for its 16 rows (17 boundary values)
        int o1 = g_off[ch * OUT_DIM + rbase + olane];
        int S = __shfl_sync(0xffffffffu, o1, 0);
        int E = __shfl_sync(0xffffffffu, o1, 16);

        // stage entry span (warp-private) + 2 pad entries for the prefetcher
        for (int k = S + lane; k < E; k += 32) {
            int d = k - S;
            if (d < EBCAP - 2) eb[d] = g_ent[k];
        }
        if (lane == 0) {
            int L = E - S; if (L > EBCAP - 2) L = EBCAP - 2;
            eb[L] = 0u; eb[L + 1] = 0u;     // safe address, never FFMA'd
        }

        // load x chunk: 256 c x 128 n (each thread: 64 LDG.32 -> 32 STS.64)
        const float* xg = xg0 + (size_t)ch * CHUNK;
        #pragma unroll 8
        for (int k = 0; k < 32; ++k) {
            float a = xg[(size_t)(2 * k) * IN_DIM];
            float b = xg[(size_t)(2 * k + 1) * IN_DIM];
            xsd[k] = make_float2(a, b);
        }
        __syncthreads();                    // xs + eb ready

        // flat pipelined gather + FFMA accumulate
        const float2* xb = xs2 + lane;
        int j = S;
        unsigned tA = eb[0];
        unsigned tB = eb[1];
        unsigned mA = tA & 0x7fffffffu;
        float2 vA0 = xb[mA];
        float2 vA1 = xb[mA + 32];
        #pragma unroll
        for (int i = 0; i < 16; ++i) {
            int e = __shfl_sync(0xffffffffu, o1, i + 1);
            while (j < e) {
                unsigned mB = tB & 0x7fffffffu;
                float2 vB0 = xb[mB];            // x for entry j+1
                float2 vB1 = xb[mB + 32];
                unsigned tC = eb[j + 2 - S];    // entry j+2
                float sg = __int_as_float(0x3f800000u | (tA & 0x80000000u));
                acc[i][0].x = fmaf(sg, vA0.x, acc[i][0].x);
                acc[i][0].y = fmaf(sg, vA0.y, acc[i][0].y);
                acc[i][1].x = fmaf(sg, vA1.x, acc[i][1].x);
                acc[i][1].y = fmaf(sg, vA1.y, acc[i][1].y);
                tA = tB; vA0 = vB0; vA1 = vB1; tB = tC;
                ++j;
            }
        }
    }
    __syncthreads();

    // epilogue: stage [256 r][130-float pitch] in xs, then coalesced stores
    float* ob = (float*)xs2;
    #pragma unroll
    for (int i = 0; i < 16; ++i) {
        int rl = (w << 4) + i;
        float2* row = (float2*)(ob + rl * 130);
        row[lane]      = make_float2(acc[i][0].x * SCALE, acc[i][0].y * SCALE);
        row[lane + 32] = make_float2(acc[i][1].x * SCALE, acc[i][1].y * SCALE);
    }
    __syncthreads();

    int rr = tid & 255;
    int nn = tid >> 8;
    float* op = out + (size_t)n0 * OUT_DIM + (rq << 8) + rr;
    #pragma unroll 16
    for (int k = 0; k < 64; ++k) {
        int n = nn * 64 + k;
        op[(size_t)n * OUT_DIM] = ob[rr * 130 + n];
    }
}

// ---------------------------------------------------------------------------
extern "C" void kernel_launch(void* const* d_in, const int* in_sizes, int n_in,
                              void* d_out, int out_size) {
    const float* x   = (const float*)d_in[0];
    const float* Phi = (const float*)d_in[1];
    float* out = (float*)d_out;

    cudaFuncSetAttribute(jl_main, cudaFuncAttributeMaxDynamicSharedMemorySize,
                         SMEM_BYTES);

    jl_count<<<128, 256>>>(Phi);
    jl_scan<<<1, 1024>>>();
    jl_fill<<<128, 256>>>(Phi);
    jl_main<<<512, 512, SMEM_BYTES>>>(x, out);
}

// round 14
// speedup vs baseline: 1.1375x; 1.0923x over previous
#include <cuda_runtime.h>
#include <cstdint>

#define IN_DIM    4096
#define OUT_DIM   1024
#define NROWS     16384
#define NCHUNK    16
#define CHUNK     256              // columns per shared chunk
#define CPITCH    132              // floats per column (33 float4, odd -> conflict-free)
#define CPITCH_B  (CPITCH * 4)     // 528 bytes per column
#define XS_FLOATS (CHUNK * CPITCH) // 33792 floats = 135168 B
#define EBCAP     128
#define NWARPS    32
#define SMEM_BYTES (XS_FLOATS * 4 + NWARPS * EBCAP * 4)  // 135168 + 16384 = 151552
#define SCALE     0.3162277660168379f   // 1/sqrt(10)

// Entry: low 31 bits = byte offset of column in chunk plane (c_local * 528), bit31 = sign.
__device__ unsigned int g_ent[40960];
__device__ int g_cnt[NCHUNK * OUT_DIM];
__device__ int g_off[NCHUNK * OUT_DIM + 1];

// ---------------------------------------------------------------------------
// Prep 1: count nonzeros per (chunk, output-row) cell. One warp per row.
__global__ void jl_count(const float* __restrict__ Phi) {
    int w = threadIdx.x >> 5, lane = threadIdx.x & 31;
    int r = blockIdx.x * 8 + w;
    const float* row = Phi + (size_t)r * IN_DIM;
    #pragma unroll
    for (int ch = 0; ch < NCHUNK; ++ch) {
        int c = 0;
        #pragma unroll
        for (int b = 0; b < CHUNK; b += 32) {
            float v = row[ch * CHUNK + b + lane];
            unsigned m = __ballot_sync(0xffffffffu, v != 0.0f);
            c += __popc(m);
        }
        if (lane == 0) g_cnt[ch * OUT_DIM + r] = c;
    }
}

// ---------------------------------------------------------------------------
// Prep 2: exclusive scan over the 16384 cell counts (chunk-major order).
__global__ void jl_scan() {
    __shared__ int sh[1024];
    int t = threadIdx.x;
    int loc[16];
    int s = 0;
    #pragma unroll
    for (int q = 0; q < 16; ++q) { loc[q] = s; s += g_cnt[t * 16 + q]; }
    sh[t] = s;
    __syncthreads();
    for (int d = 1; d < 1024; d <<= 1) {
        int v = 0;
        if (t >= d) v = sh[t - d];
        __syncthreads();
        sh[t] += v;
        __syncthreads();
    }
    int ex = (t == 0) ? 0 : sh[t - 1];
    #pragma unroll
    for (int q = 0; q < 16; ++q) g_off[t * 16 + q] = ex + loc[q];
    if (t == 1023) g_off[NCHUNK * OUT_DIM] = sh[1023];
}

// ---------------------------------------------------------------------------
// Prep 3: fill compact chunk-major entry array (ballot/popc compaction).
__global__ void jl_fill(const float* __restrict__ Phi) {
    int w = threadIdx.x >> 5, lane = threadIdx.x & 31;
    int r = blockIdx.x * 8 + w;
    const float* row = Phi + (size_t)r * IN_DIM;
    unsigned lmask = (1u << lane) - 1u;
    for (int ch = 0; ch < NCHUNK; ++ch) {
        int pos = g_off[ch * OUT_DIM + r];
        for (int b = 0; b < CHUNK; b += 32) {
            float v = row[ch * CHUNK + b + lane];
            bool nz = (v != 0.0f);
            unsigned m = __ballot_sync(0xffffffffu, nz);
            if (nz) {
                int idx = pos + __popc(m & lmask);
                unsigned cl = (unsigned)(b + lane);          // c within chunk, 0..255
                g_ent[idx] = cl * CPITCH_B + (v < 0.0f ? 0x80000000u : 0u);
            }
            pos += __popc(m);
        }
    }
}

// ---------------------------------------------------------------------------
// Gather over rows i = 0..7 for entries j in [max(b_i,LO), min(e_i,HI)),
// entry source SRC indexed by (j - BASE).
#define GATHER_ROWS(SRC, BASE, LO, HI)                                        \
    {                                                                         \
        _Pragma("unroll")                                                     \
        for (int i = 0; i < 8; ++i) {                                         \
            int jb = __shfl_sync(0xffffffffu, o1, i);                         \
            int je = __shfl_sync(0xffffffffu, o1, i + 1);                     \
            if (jb < (LO)) jb = (LO);                                         \
            if (je > (HI)) je = (HI);                                         \
            for (int j = jb; j < je; ++j) {                                   \
                unsigned t = (SRC)[j - (BASE)];                               \
                const float4* p = (const float4*)(xbase + (t & 0x7fffffffu)); \
                float4 v = *p;                                                \
                float sg = __int_as_float(0x3f800000u | (t & 0x80000000u));   \
                acc[i].x = fmaf(sg, v.x, acc[i].x);                           \
                acc[i].y = fmaf(sg, v.y, acc[i].y);                           \
                acc[i].z = fmaf(sg, v.z, acc[i].z);                           \
                acc[i].w = fmaf(sg, v.w, acc[i].w);                           \
            }                                                                 \
        }                                                                     \
    }

// Main: 512 blocks = 128 n-tiles x 4 row-quarters. Block = 1024 thr (32 warps,
// occ 50%), covers 128 n x 256 output rows. Warp owns 8 rows; lane l covers
// n = 4l..4l+3 (acc = 8 float4 = 32 regs). x chunk in shared as
// [256 c][pitch 132 floats]: STS.128 fill and LDS.128 broadcast gather are
// both conflict-free (addr16 mod 8 = c mod 8 / lane mod 8; pitch16 = 33 odd).
__global__ __launch_bounds__(1024, 1) void jl_main(const float* __restrict__ x,
                                                   float* __restrict__ out) {
    extern __shared__ float xs[];
    unsigned* eb_all = (unsigned*)(xs + XS_FLOATS);
    int tid  = threadIdx.x;
    int lane = tid & 31, w = tid >> 5;
    int nt = blockIdx.x >> 2, rq = blockIdx.x & 3;
    int n0 = nt << 7;                        // 128 n per block
    int rbase = (rq << 8) + (w << 3);        // this warp's 8 rows
    unsigned* eb = eb_all + w * EBCAP;

    float4 acc[8];
    #pragma unroll
    for (int i = 0; i < 8; ++i) acc[i] = make_float4(0.f, 0.f, 0.f, 0.f);

    // x-fill mapping: thread = (column cc, n-subgroup ng of 32 n).
    int cc = tid & 255;
    int ng = tid >> 8;                       // 0..3
    const float* xg0 = x + (size_t)(n0 + ng * 32) * IN_DIM + cc;
    float4* xsd = (float4*)xs + cc * (CPITCH / 4) + ng * 8;

    int olane = (lane < 9) ? lane : 8;       // lanes 0..8 carry segment offsets
    const char* xbase = (const char*)xs + lane * 16;

    for (int ch = 0; ch < NCHUNK; ++ch) {
        if (ch) __syncthreads();             // xs/eb free (previous gather done)

        int o1 = g_off[ch * OUT_DIM + rbase + olane];
        int S = __shfl_sync(0xffffffffu, o1, 0);
        int E = __shfl_sync(0xffffffffu, o1, 8);

        // stage entry span (warp-private)
        for (int k = S + lane; k < E; k += 32) {
            int d = k - S;
            if (d < EBCAP) eb[d] = g_ent[k];
        }

        // fill x chunk: 256 c x 128 n. Per thread: 32 LDG.32 -> 8 STS.128.
        const float* xg = xg0 + ch * CHUNK;
        #pragma unroll
        for (int g = 0; g < 8; ++g) {
            const float* p = xg + (size_t)(4 * g) * IN_DIM;
            float4 v;
            v.x = p[0];
            v.y = p[IN_DIM];
            v.z = p[2 * IN_DIM];
            v.w = p[3 * IN_DIM];
            xsd[g] = v;
        }
        __syncthreads();                     // xs + eb ready

        // gather + FFMA (fast path: all staged; overflow path ~never taken)
        int hi = S + EBCAP;
        if (E <= hi) {
            GATHER_ROWS(eb, S, S, E);
        } else {
            GATHER_ROWS(eb, S, S, hi);
            GATHER_ROWS(g_ent, 0, hi, E);
        }
    }
    __syncthreads();

    // epilogue: stage [256 r][pitch 65 float2] in xs, then coalesced stores
    float2* xs2 = (float2*)xs;
    #pragma unroll
    for (int i = 0; i < 8; ++i) {
        int rl = (w << 3) + i;
        float2* orow = xs2 + rl * 65;
        orow[2 * lane]     = make_float2(acc[i].x * SCALE, acc[i].y * SCALE);
        orow[2 * lane + 1] = make_float2(acc[i].z * SCALE, acc[i].w * SCALE);
    }
    __syncthreads();

    int rr = tid & 255;
    int ng2 = tid >> 8;                      // 0..3, 16 float2 (32 n) each
    const float2* src = xs2 + rr * 65 + ng2 * 16;
    float* op = out + (size_t)n0 * OUT_DIM + (rq << 8) + rr;
    #pragma unroll
    for (int k = 0; k < 16; ++k) {
        float2 v = src[k];
        int n = (ng2 * 16 + k) * 2;
        op[(size_t)n * OUT_DIM]       = v.x;
        op[(size_t)(n + 1) * OUT_DIM] = v.y;
    }
}

// ---------------------------------------------------------------------------
extern "C" void kernel_launch(void* const* d_in, const int* in_sizes, int n_in,
                              void* d_out, int out_size) {
    const float* x   = (const float*)d_in[0];
    const float* Phi = (const float*)d_in[1];
    float* out = (float*)d_out;

    cudaFuncSetAttribute(jl_main, cudaFuncAttributeMaxDynamicSharedMemorySize,
                         SMEM_BYTES);

    jl_count<<<128, 256>>>(Phi);
    jl_scan<<<1, 1024>>>();
    jl_fill<<<128, 256>>>(Phi);
    jl_main<<<512, 1024, SMEM_BYTES>>>(x, out);
}

// round 15
// speedup vs baseline: 1.1724x; 1.0308x over previous
#include <cuda_runtime.h>
#include <cstdint>

#define IN_DIM    4096
#define OUT_DIM   1024
#define NROWS     16384
#define NCHUNK    16
#define CHUNK     256               // columns per shared chunk
#define CPITCH    132               // floats per column (pitch16 = 33, odd -> conflict-free)
#define CPITCH_B  (CPITCH * 4)      // 528 bytes per column
#define XS_FLOATS ((CHUNK + 1) * CPITCH)   // +1 zero column; 33924 floats = 135696 B
#define SMEM_BYTES (XS_FLOATS * 4)
#define ZPAD      ((unsigned)(CHUNK * CPITCH_B))   // byte offset of zero column, sign +
#define SCALE     0.3162277660168379f   // 1/sqrt(10)

// Padded structure: exactly 4 entries per (chunk,row) cell, pad = ZPAD.
// Entry: low 31 bits = column byte offset in chunk plane (c_local*528), bit31 = sign.
__device__ uint4     g_pad[NCHUNK * OUT_DIM];      // [ch][row] -> 4 entries (256 KB)
__device__ unsigned  g_ent2[40960];                // overflow entries (idx >= 4 in cell)
__device__ int       g_cnt[NCHUNK * OUT_DIM];      // full per-cell counts
__device__ int       g_off2[NCHUNK * OUT_DIM + 1]; // scan of max(cnt-4,0)

// ---------------------------------------------------------------------------
// Prep 1: count nonzeros per (chunk, output-row) cell. One warp per row.
__global__ void jl_count(const float* __restrict__ Phi) {
    int w = threadIdx.x >> 5, lane = threadIdx.x & 31;
    int r = blockIdx.x * 8 + w;
    const float* row = Phi + (size_t)r * IN_DIM;
    #pragma unroll
    for (int ch = 0; ch < NCHUNK; ++ch) {
        int c = 0;
        #pragma unroll
        for (int b = 0; b < CHUNK; b += 32) {
            float v = row[ch * CHUNK + b + lane];
            unsigned m = __ballot_sync(0xffffffffu, v != 0.0f);
            c += __popc(m);
        }
        if (lane == 0) g_cnt[ch * OUT_DIM + r] = c;
    }
}

// ---------------------------------------------------------------------------
// Prep 2: exclusive scan over OVERFLOW counts max(cnt-4,0), chunk-major.
__global__ void jl_scan() {
    __shared__ int sh[1024];
    int t = threadIdx.x;
    int loc[16];
    int s = 0;
    #pragma unroll
    for (int q = 0; q < 16; ++q) {
        loc[q] = s;
        int c = g_cnt[t * 16 + q] - 4;
        s += (c > 0) ? c : 0;
    }
    sh[t] = s;
    __syncthreads();
    for (int d = 1; d < 1024; d <<= 1) {
        int v = 0;
        if (t >= d) v = sh[t - d];
        __syncthreads();
        sh[t] += v;
        __syncthreads();
    }
    int ex = (t == 0) ? 0 : sh[t - 1];
    #pragma unroll
    for (int q = 0; q < 16; ++q) g_off2[t * 16 + q] = ex + loc[q];
    if (t == 1023) g_off2[NCHUNK * OUT_DIM] = sh[1023];
}

// ---------------------------------------------------------------------------
// Prep 3: fill padded-4 records + overflow list (ballot/popc, deterministic).
__global__ void jl_fill(const float* __restrict__ Phi) {
    int w = threadIdx.x >> 5, lane = threadIdx.x & 31;
    int r = blockIdx.x * 8 + w;
    const float* row = Phi + (size_t)r * IN_DIM;
    unsigned* padw = (unsigned*)g_pad;
    unsigned lmask = (1u << lane) - 1u;
    for (int ch = 0; ch < NCHUNK; ++ch) {
        int cell = ch * OUT_DIM + r;
        int base2 = g_off2[cell];
        int lpos = 0;
        for (int b = 0; b < CHUNK; b += 32) {
            float v = row[ch * CHUNK + b + lane];
            bool nz = (v != 0.0f);
            unsigned m = __ballot_sync(0xffffffffu, nz);
            if (nz) {
                int ip = lpos + __popc(m & lmask);
                unsigned e = (unsigned)(b + lane) * CPITCH_B
                           + (v < 0.0f ? 0x80000000u : 0u);
                if (ip < 4) padw[cell * 4 + ip] = e;
                else        g_ent2[base2 + ip - 4] = e;
            }
            lpos += __popc(m);
        }
        // pad remaining slots lpos..3 (lane index = slot index)
        if (lane >= lpos && lane < 4) padw[cell * 4 + lane] = ZPAD;
    }
}

// ---------------------------------------------------------------------------
// One padded row: 4 shfl'd entries -> 4 conflict-free LDS.128 + 16 FFMA.
#define DO_ROW(I)                                                             \
    {                                                                         \
        unsigned t0 = __shfl_sync(0xffffffffu, pe.x, (I));                    \
        unsigned t1 = __shfl_sync(0xffffffffu, pe.y, (I));                    \
        unsigned t2 = __shfl_sync(0xffffffffu, pe.z, (I));                    \
        unsigned t3 = __shfl_sync(0xffffffffu, pe.w, (I));                    \
        float4 v0 = *(const float4*)(xbase + (t0 & 0x7fffffffu));             \
        float4 v1 = *(const float4*)(xbase + (t1 & 0x7fffffffu));             \
        float4 v2 = *(const float4*)(xbase + (t2 & 0x7fffffffu));             \
        float4 v3 = *(const float4*)(xbase + (t3 & 0x7fffffffu));             \
        float s0 = __int_as_float(0x3f800000u | (t0 & 0x80000000u));          \
        float s1 = __int_as_float(0x3f800000u | (t1 & 0x80000000u));          \
        float s2 = __int_as_float(0x3f800000u | (t2 & 0x80000000u));          \
        float s3 = __int_as_float(0x3f800000u | (t3 & 0x80000000u));          \
        acc[I].x = fmaf(s0, v0.x, acc[I].x);                                  \
        acc[I].y = fmaf(s0, v0.y, acc[I].y);                                  \
        acc[I].z = fmaf(s0, v0.z, acc[I].z);                                  \
        acc[I].w = fmaf(s0, v0.w, acc[I].w);                                  \
        acc[I].x = fmaf(s1, v1.x, acc[I].x);                                  \
        acc[I].y = fmaf(s1, v1.y, acc[I].y);                                  \
        acc[I].z = fmaf(s1, v1.z, acc[I].z);                                  \
        acc[I].w = fmaf(s1, v1.w, acc[I].w);                                  \
        acc[I].x = fmaf(s2, v2.x, acc[I].x);                                  \
        acc[I].y = fmaf(s2, v2.y, acc[I].y);                                  \
        acc[I].z = fmaf(s2, v2.z, acc[I].z);                                  \
        acc[I].w = fmaf(s2, v2.w, acc[I].w);                                  \
        acc[I].x = fmaf(s3, v3.x, acc[I].x);                                  \
        acc[I].y = fmaf(s3, v3.y, acc[I].y);                                  \
        acc[I].z = fmaf(s3, v3.z, acc[I].z);                                  \
        acc[I].w = fmaf(s3, v3.w, acc[I].w);                                  \
    }

// Main: 512 blocks = 128 n-tiles x 4 row-quarters. Block = 1024 thr (32 warps,
// occ 50%), covers 128 n x 256 output rows. Warp owns 8 rows; lane l covers
// n = 4l..4l+3 (acc = 8 float4 = 32 regs). x chunk in shared as
// [257 c][pitch 132 floats] (column 256 zeroed, target of pad entries).
// Inner loop per chunk is a BRANCH-FREE fully unrolled 8x4 block: entries
// arrive via one coalesced LDG.128 (prefetched a chunk ahead) + SHFL.
__global__ __launch_bounds__(1024, 1) void jl_main(const float* __restrict__ x,
                                                   float* __restrict__ out) {
    extern __shared__ float xs[];
    int tid  = threadIdx.x;
    int lane = tid & 31, w = tid >> 5;
    int nt = blockIdx.x >> 2, rq = blockIdx.x & 3;
    int n0 = nt << 7;                        // 128 n per block
    int rbase = (rq << 8) + (w << 3);        // this warp's 8 rows

    float4 acc[8];
    #pragma unroll
    for (int i = 0; i < 8; ++i) acc[i] = make_float4(0.f, 0.f, 0.f, 0.f);

    // zero column (pad target)
    if (tid < CPITCH) xs[CHUNK * CPITCH + tid] = 0.0f;

    // x-fill mapping: thread = (column cc, n-subgroup ng of 32 n).
    int cc = tid & 255;
    int ng = tid >> 8;                       // 0..3
    const float* xg0 = x + (size_t)(n0 + ng * 32) * IN_DIM + cc;
    float4* xsd = (float4*)xs + cc * (CPITCH / 4) + ng * 8;

    int myrow = rbase + (lane & 7);          // all lanes mirror rows 0..7
    int olane = (lane < 9) ? lane : 8;       // lanes 0..8 carry overflow offsets
    const char* xbase = (const char*)xs + lane * 16;

    // prefetch chunk 0 entry record + overflow offsets
    uint4 pe = g_pad[myrow];                 // ch = 0
    int o1x = g_off2[rbase + olane];         // ch = 0

    for (int ch = 0; ch < NCHUNK; ++ch) {
        if (ch) __syncthreads();             // xs free (previous gather done)

        // fill x chunk: 256 c x 128 n. Per thread: 32 LDG.32 -> 8 STS.128.
        const float* xg = xg0 + ch * CHUNK;
        #pragma unroll
        for (int g = 0; g < 8; ++g) {
            const float* p = xg + (size_t)(4 * g) * IN_DIM;
            float4 v;
            v.x = p[0];
            v.y = p[IN_DIM];
            v.z = p[2 * IN_DIM];
            v.w = p[3 * IN_DIM];
            xsd[g] = v;
        }

        // prefetch next chunk's records (latency hides under fill + gather)
        uint4 pe_nxt = pe;
        int o1x_nxt = o1x;
        if (ch + 1 < NCHUNK) {
            pe_nxt  = g_pad[((ch + 1) << 10) + myrow];
            o1x_nxt = g_off2[((ch + 1) << 10) + rbase + olane];
        }
        __syncthreads();                     // xs ready

        // ---- static branch-free gather: 8 rows x 4 entries ----
        DO_ROW(0) DO_ROW(1) DO_ROW(2) DO_ROW(3)
        DO_ROW(4) DO_ROW(5) DO_ROW(6) DO_ROW(7)

        // ---- rare overflow entries (cells with >4 nonzeros) ----
        int S0 = __shfl_sync(0xffffffffu, o1x, 0);
        int E0 = __shfl_sync(0xffffffffu, o1x, 8);
        if (E0 > S0) {
            #pragma unroll
            for (int i = 0; i < 8; ++i) {
                int jb = __shfl_sync(0xffffffffu, o1x, i);
                int je = __shfl_sync(0xffffffffu, o1x, i + 1);
                for (int j = jb; j < je; ++j) {
                    unsigned t = g_ent2[j];
                    float4 v = *(const float4*)(xbase + (t & 0x7fffffffu));
                    float sg = __int_as_float(0x3f800000u | (t & 0x80000000u));
                    acc[i].x = fmaf(sg, v.x, acc[i].x);
                    acc[i].y = fmaf(sg, v.y, acc[i].y);
                    acc[i].z = fmaf(sg, v.z, acc[i].z);
                    acc[i].w = fmaf(sg, v.w, acc[i].w);
                }
            }
        }
        pe = pe_nxt;
        o1x = o1x_nxt;
    }
    __syncthreads();

    // epilogue: stage [256 r][pitch 65 float2] in xs, then coalesced stores
    float2* xs2 = (float2*)xs;
    #pragma unroll
    for (int i = 0; i < 8; ++i) {
        int rl = (w << 3) + i;
        float2* orow = xs2 + rl * 65;
        orow[2 * lane]     = make_float2(acc[i].x * SCALE, acc[i].y * SCALE);
        orow[2 * lane + 1] = make_float2(acc[i].z * SCALE, acc[i].w * SCALE);
    }
    __syncthreads();

    int rr = tid & 255;
    int ng2 = tid >> 8;                      // 0..3, 16 float2 (32 n) each
    const float2* src = xs2 + rr * 65 + ng2 * 16;
    float* op = out + (size_t)n0 * OUT_DIM + (rq << 8) + rr;
    #pragma unroll
    for (int k = 0; k < 16; ++k) {
        float2 v = src[k];
        int n = (ng2 * 16 + k) * 2;
        op[(size_t)n * OUT_DIM]       = v.x;
        op[(size_t)(n + 1) * OUT_DIM] = v.y;
    }
}

// ---------------------------------------------------------------------------
extern "C" void kernel_launch(void* const* d_in, const int* in_sizes, int n_in,
                              void* d_out, int out_size) {
    const float* x   = (const float*)d_in[0];
    const float* Phi = (const float*)d_in[1];
    float* out = (float*)d_out;

    cudaFuncSetAttribute(jl_main, cudaFuncAttributeMaxDynamicSharedMemorySize,
                         SMEM_BYTES);

    jl_count<<<128, 256>>>(Phi);
    jl_scan<<<1, 1024>>>();
    jl_fill<<<128, 256>>>(Phi);
    jl_main<<<512, 1024, SMEM_BYTES>>>(x, out);
}

// round 16
// speedup vs baseline: 1.1824x; 1.0085x over previous
#include <cuda_runtime.h>
#include <cstdint>

#define IN_DIM    4096
#define OUT_DIM   1024
#define NCHUNK    16
#define CHUNK     256               // columns per shared chunk
#define CPITCH    132               // floats per column (pitch16 = 33, odd -> conflict-free)
#define CPITCH_B  (CPITCH * 4)      // 528 bytes per column
#define XS_FLOATS ((CHUNK + 1) * CPITCH)   // +1 zero column for pads
#define SMEM_BYTES (XS_FLOATS * 4)
#define ZPAD      ((unsigned)(CHUNK * CPITCH_B))   // byte offset of zero column
#define OVF_SLOTS 16
#define SCALE     0.3162277660168379f   // 1/sqrt(10)

// Padded structure: exactly 4 entries per (chunk,row) cell, pad = ZPAD.
// Entry: low 31 bits = column byte offset in chunk plane (c_local*528), bit31 = sign.
__device__ uint4     g_pad[NCHUNK * OUT_DIM];                // 256 KB
__device__ unsigned  g_ovf[NCHUNK * OUT_DIM * OVF_SLOTS];    // overflow slots, 1 MB
__device__ int       g_ovfcnt[NCHUNK * OUT_DIM];             // clamped overflow counts

// ---------------------------------------------------------------------------
// Single prep kernel: padded-4 records + fixed-slot overflow (ballot/popc,
// deterministic, no scan needed). One warp per output row.
__global__ void jl_fill(const float* __restrict__ Phi) {
    int w = threadIdx.x >> 5, lane = threadIdx.x & 31;
    int r = blockIdx.x * 8 + w;
    const float* row = Phi + (size_t)r * IN_DIM;
    unsigned* padw = (unsigned*)g_pad;
    unsigned lmask = (1u << lane) - 1u;
    for (int ch = 0; ch < NCHUNK; ++ch) {
        int cell = ch * OUT_DIM + r;
        int lpos = 0;
        for (int b = 0; b < CHUNK; b += 32) {
            float v = row[ch * CHUNK + b + lane];
            bool nz = (v != 0.0f);
            unsigned m = __ballot_sync(0xffffffffu, nz);
            if (nz) {
                int ip = lpos + __popc(m & lmask);
                unsigned e = (unsigned)(b + lane) * CPITCH_B
                           + (v < 0.0f ? 0x80000000u : 0u);
                if (ip < 4) padw[cell * 4 + ip] = e;
                else if (ip - 4 < OVF_SLOTS) g_ovf[cell * OVF_SLOTS + ip - 4] = e;
            }
            lpos += __popc(m);
        }
        if (lane >= lpos && lane < 4) padw[cell * 4 + lane] = ZPAD;  // pad slots
        if (lane == 0) {
            int c = lpos - 4;
            if (c < 0) c = 0;
            if (c > OVF_SLOTS) c = OVF_SLOTS;
            g_ovfcnt[cell] = c;
        }
    }
}

// ---------------------------------------------------------------------------
// Predicated shared load: no wavefront (and no crossbar cost) when T == ZPAD.
// V must be pre-zeroed; ptxas keeps the @p form (no BSSY) since we author PTX.
#define PLDS(V, T, ADDR)                                                      \
    asm volatile("{\n\t"                                                      \
        ".reg .pred p;\n\t"                                                   \
        "setp.ne.u32 p, %4, %5;\n\t"                                          \
        "@p ld.shared.v4.f32 {%0,%1,%2,%3}, [%6];\n\t"                        \
        "}" : "+f"((V).x), "+f"((V).y), "+f"((V).z), "+f"((V).w)              \
            : "r"(T), "r"(ZPAD), "r"(ADDR));

// One padded row: 4 shfl'd entries -> up to 4 predicated LDS.128 + 16 FFMA.
#define DO_ROW(I)                                                             \
    {                                                                         \
        unsigned t0 = __shfl_sync(0xffffffffu, pe.x, (I));                    \
        unsigned t1 = __shfl_sync(0xffffffffu, pe.y, (I));                    \
        unsigned t2 = __shfl_sync(0xffffffffu, pe.z, (I));                    \
        unsigned t3 = __shfl_sync(0xffffffffu, pe.w, (I));                    \
        float4 v0 = make_float4(0.f,0.f,0.f,0.f);                             \
        float4 v1 = v0, v2 = v0, v3 = v0;                                     \
        PLDS(v0, t0, xs_s + (t0 & 0x7fffffffu))                               \
        PLDS(v1, t1, xs_s + (t1 & 0x7fffffffu))                               \
        PLDS(v2, t2, xs_s + (t2 & 0x7fffffffu))                               \
        PLDS(v3, t3, xs_s + (t3 & 0x7fffffffu))                               \
        float s0 = __int_as_float(0x3f800000u | (t0 & 0x80000000u));          \
        float s1 = __int_as_float(0x3f800000u | (t1 & 0x80000000u));          \
        float s2 = __int_as_float(0x3f800000u | (t2 & 0x80000000u));          \
        float s3 = __int_as_float(0x3f800000u | (t3 & 0x80000000u));          \
        acc[I].x = fmaf(s0, v0.x, acc[I].x);                                  \
        acc[I].y = fmaf(s0, v0.y, acc[I].y);                                  \
        acc[I].z = fmaf(s0, v0.z, acc[I].z);                                  \
        acc[I].w = fmaf(s0, v0.w, acc[I].w);                                  \
        acc[I].x = fmaf(s1, v1.x, acc[I].x);                                  \
        acc[I].y = fmaf(s1, v1.y, acc[I].y);                                  \
        acc[I].z = fmaf(s1, v1.z, acc[I].z);                                  \
        acc[I].w = fmaf(s1, v1.w, acc[I].w);                                  \
        acc[I].x = fmaf(s2, v2.x, acc[I].x);                                  \
        acc[I].y = fmaf(s2, v2.y, acc[I].y);                                  \
        acc[I].z = fmaf(s2, v2.z, acc[I].z);                                  \
        acc[I].w = fmaf(s2, v2.w, acc[I].w);                                  \
        acc[I].x = fmaf(s3, v3.x, acc[I].x);                                  \
        acc[I].y = fmaf(s3, v3.y, acc[I].y);                                  \
        acc[I].z = fmaf(s3, v3.z, acc[I].z);                                  \
        acc[I].w = fmaf(s3, v3.w, acc[I].w);                                  \
    }

// Main: 512 blocks = 128 n-tiles x 4 row-quarters. Block = 1024 thr (32 warps,
// occ 50%), covers 128 n x 256 output rows. Warp owns 8 rows; lane l covers
// n = 4l..4l+3 (acc = 8 float4 = 32 regs). x chunk in shared as
// [257 c][pitch 132 floats] (column 256 zeroed, target of pad entries).
// Gather is branch-free 8x4 predicated block; overflow entries (cells with
// >4 nnz) are register-prefetched a chunk ahead (slots 0..3/row, covers
// X<=8; deeper cells fall back to a direct global loop, ~0.9% of warp-chunks).
__global__ __launch_bounds__(1024, 1) void jl_main(const float* __restrict__ x,
                                                   float* __restrict__ out) {
    extern __shared__ float xs[];
    int tid  = threadIdx.x;
    int lane = tid & 31, w = tid >> 5;
    int nt = blockIdx.x >> 2, rq = blockIdx.x & 3;
    int n0 = nt << 7;                        // 128 n per block
    int rbase = (rq << 8) + (w << 3);        // this warp's 8 rows

    float4 acc[8];
    #pragma unroll
    for (int i = 0; i < 8; ++i) acc[i] = make_float4(0.f, 0.f, 0.f, 0.f);

    // zero column (pad target)
    if (tid < CPITCH) xs[CHUNK * CPITCH + tid] = 0.0f;

    // x-fill mapping: thread = (column cc, n-subgroup ng of 32 n).
    int cc = tid & 255;
    int ng = tid >> 8;                       // 0..3
    const float* xg0 = x + (size_t)(n0 + ng * 32) * IN_DIM + cc;
    float4* xsd = (float4*)xs + cc * (CPITCH / 4) + ng * 8;

    int myrow = rbase + (lane & 7);          // all lanes mirror rows 0..7
    unsigned xs_s = (unsigned)__cvta_generic_to_shared(xs) + (unsigned)(lane * 16);
    const char* xbase = (const char*)xs + lane * 16;
    int ovrow = rbase + (lane >> 2);         // lane 4i+k -> row i, slot k
    int ovslot = lane & 3;

    // prefetch chunk 0 records
    uint4 pe = g_pad[myrow];
    int ocnt = (lane < 8) ? g_ovfcnt[rbase + lane] : 0;
    unsigned ov = g_ovf[ovrow * OVF_SLOTS + ovslot];

    for (int ch = 0; ch < NCHUNK; ++ch) {
        if (ch) __syncthreads();             // xs free (previous gather done)

        // fill x chunk: 256 c x 128 n. Per thread: 32 LDG.32 -> 8 STS.128.
        const float* xg = xg0 + ch * CHUNK;
        #pragma unroll
        for (int g = 0; g < 8; ++g) {
            const float* p = xg + (size_t)(4 * g) * IN_DIM;
            float4 v;
            v.x = p[0];
            v.y = p[IN_DIM];
            v.z = p[2 * IN_DIM];
            v.w = p[3 * IN_DIM];
            xsd[g] = v;
        }

        // prefetch next chunk's records (latency hides under fill + gather)
        uint4 pe_nxt = pe;
        int ocnt_nxt = ocnt;
        unsigned ov_nxt = ov;
        if (ch + 1 < NCHUNK) {
            int cb = (ch + 1) << 10;
            pe_nxt   = g_pad[cb + myrow];
            ocnt_nxt = (lane < 8) ? g_ovfcnt[cb + rbase + lane] : 0;
            ov_nxt   = g_ovf[(cb + ovrow) * OVF_SLOTS + ovslot];
        }
        __syncthreads();                     // xs ready

        // ---- static predicated gather: 8 rows x 4 entries ----
        DO_ROW(0) DO_ROW(1) DO_ROW(2) DO_ROW(3)
        DO_ROW(4) DO_ROW(5) DO_ROW(6) DO_ROW(7)

        // ---- overflow entries (cells with >4 nonzeros), register-resident ----
        unsigned anyov = __ballot_sync(0xffffffffu, (lane < 8) && (ocnt > 0));
        if (anyov) {
            #pragma unroll
            for (int i = 0; i < 8; ++i) {
                int c = __shfl_sync(0xffffffffu, ocnt, i);
                if (c) {
                    int cm = (c < 4) ? c : 4;
                    for (int k = 0; k < cm; ++k) {
                        unsigned t = __shfl_sync(0xffffffffu, ov, 4 * i + k);
                        float4 v = *(const float4*)(xbase + (t & 0x7fffffffu));
                        float sg = __int_as_float(0x3f800000u | (t & 0x80000000u));
                        acc[i].x = fmaf(sg, v.x, acc[i].x);
                        acc[i].y = fmaf(sg, v.y, acc[i].y);
                        acc[i].z = fmaf(sg, v.z, acc[i].z);
                        acc[i].w = fmaf(sg, v.w, acc[i].w);
                    }
                    if (c > 4) {             // very rare deep cell
                        const unsigned* op2 =
                            &g_ovf[((ch << 10) + rbase + i) * OVF_SLOTS];
                        for (int k = 4; k < c; ++k) {
                            unsigned t = op2[k];
                            float4 v = *(const float4*)(xbase + (t & 0x7fffffffu));
                            float sg = __int_as_float(0x3f800000u | (t & 0x80000000u));
                            acc[i].x = fmaf(sg, v.x, acc[i].x);
                            acc[i].y = fmaf(sg, v.y, acc[i].y);
                            acc[i].z = fmaf(sg, v.z, acc[i].z);
                            acc[i].w = fmaf(sg, v.w, acc[i].w);
                        }
                    }
                }
            }
        }
        pe = pe_nxt;
        ocnt = ocnt_nxt;
        ov = ov_nxt;
    }
    __syncthreads();

    // epilogue: stage [256 r][pitch 65 float2] in xs, then coalesced stores
    float2* xs2 = (float2*)xs;
    #pragma unroll
    for (int i = 0; i < 8; ++i) {
        int rl = (w << 3) + i;
        float2* orow = xs2 + rl * 65;
        orow[2 * lane]     = make_float2(acc[i].x * SCALE, acc[i].y * SCALE);
        orow[2 * lane + 1] = make_float2(acc[i].z * SCALE, acc[i].w * SCALE);
    }
    __syncthreads();

    int rr = tid & 255;
    int ng2 = tid >> 8;                      // 0..3, 16 float2 (32 n) each
    const float2* src = xs2 + rr * 65 + ng2 * 16;
    float* op = out + (size_t)n0 * OUT_DIM + (rq << 8) + rr;
    #pragma unroll
    for (int k = 0; k < 16; ++k) {
        float2 v = src[k];
        int n = (ng2 * 16 + k) * 2;
        op[(size_t)n * OUT_DIM]       = v.x;
        op[(size_t)(n + 1) * OUT_DIM] = v.y;
    }
}

// ---------------------------------------------------------------------------
extern "C" void kernel_launch(void* const* d_in, const int* in_sizes, int n_in,
                              void* d_out, int out_size) {
    const float* x   = (const float*)d_in[0];
    const float* Phi = (const float*)d_in[1];
    float* out = (float*)d_out;

    cudaFuncSetAttribute(jl_main, cudaFuncAttributeMaxDynamicSharedMemorySize,
                         SMEM_BYTES);

    jl_fill<<<128, 256>>>(Phi);
    jl_main<<<512, 1024, SMEM_BYTES>>>(x, out);
}